// round 1
// baseline (speedup 1.0000x reference)
#include <cuda_runtime.h>
#include <cstdint>

// Problem constants
#define NQ   8
#define BINS 1024
#define DIM  256
#define BB   8
#define TT   8192
#define NTOK (BB * TT)          // 65536 tokens
#define MT   128                // tokens per block
#define NBLK (NTOK / MT)        // 512 blocks
#define NC   128                // j-chunk width
#define KSL  32                 // K slice
#define RS   132                // Rsm row stride (floats), padded vs 128
#define QOFF 16777216           // quantized elements
#define CELEMS (NQ * BB * TT)   // 524288 codes
#define COFF (QOFF + CELEMS)    // scalar offset

// Shared memory layout (floats)
#define SM_R    0                       // 256*132 = 33792
#define SM_C    (256 * RS)              // 2*32*128 = 8192
#define SM_REDV (SM_C + 2 * KSL * NC)   // 128*16 = 2048
#define SM_REDI (SM_REDV + MT * 16)     // 128*16 = 2048 (int)
#define SM_SIDX (SM_REDI + MT * 16)     // 128 (int)
#define SM_SSQ  (SM_SIDX + MT)          // 256
#define SM_TOTAL_FLOATS (SM_SSQ + 256)
#define SM_BYTES (SM_TOTAL_FLOATS * 4)  // 185856 bytes

__device__ float g_cbsq[NQ * BINS];
__device__ float g_ssq[NQ * NBLK];

// ---------------------------------------------------------------------------
// Kernel 1: per-codeword squared norms
// ---------------------------------------------------------------------------
__global__ void rvq_cbsq_kernel(const float* __restrict__ cbs) {
    int id = blockIdx.x * blockDim.x + threadIdx.x;
    if (id >= NQ * BINS) return;
    const float* c = cbs + (size_t)id * DIM;
    float s0 = 0.f, s1 = 0.f, s2 = 0.f, s3 = 0.f;
    #pragma unroll 8
    for (int d = 0; d < DIM; d += 4) {
        float4 v = *(const float4*)(c + d);
        s0 = fmaf(v.x, v.x, s0);
        s1 = fmaf(v.y, v.y, s1);
        s2 = fmaf(v.z, v.z, s2);
        s3 = fmaf(v.w, v.w, s3);
    }
    g_cbsq[id] = (s0 + s1) + (s2 + s3);
}

// ---------------------------------------------------------------------------
// Kernel 2: main RVQ — residual tile resident in SMEM across all 8 steps
// ---------------------------------------------------------------------------
__global__ __launch_bounds__(256, 1)
void rvq_main_kernel(const float* __restrict__ x,
                     const float* __restrict__ cbs,
                     float* __restrict__ out) {
    extern __shared__ float sm[];
    float* Rsm  = sm + SM_R;              // [256 k][RS] (k-major, m inner)
    float* Csm  = sm + SM_C;              // 2 buffers of [32 kk][128 j]
    float* redv = sm + SM_REDV;           // [128 m][16]
    int*   redi = (int*)(sm + SM_REDI);   // [128 m][16]
    int*   sidx = (int*)(sm + SM_SIDX);   // [128]
    float* ssqs = sm + SM_SSQ;            // [256]

    const int tid = threadIdx.x;
    const int bid = blockIdx.x;
    const int b   = bid >> 6;             // 64 tiles per batch row
    const int t0  = (bid & 63) << 7;
    const float* xblk = x + ((size_t)b * DIM) * TT + t0;

    // Load x tile: Rsm[d][m] = x[b][d][t0+m]  (coalesced over m)
    for (int i = tid; i < DIM * MT; i += 256) {
        int d = i >> 7, m = i & 127;
        Rsm[d * RS + m] = xblk[(size_t)d * TT + m];
    }
    __syncthreads();

    // GEMM thread mapping: 8 warps = 4 (m) x 2 (j); lane = 4 (mi) x 8 (ji)
    const int lane = tid & 31, warp = tid >> 5;
    const int mi = lane & 3, ji = lane >> 2;
    const int tm = (warp & 3) * 4 + mi;   // 0..15 -> tokens tm*8..+7
    const int tj = (warp >> 2) * 8 + ji;  // 0..15 -> j offs tj*8..+7
    const int aoff = tm * 8;
    const int boff = tj * 8;

    // Loader mapping for C slices
    const int lj = tid >> 3;              // 0..31 row-in-group
    const int lg = tid & 7;               // 0..7 -> float4 column

    for (int q = 0; q < NQ; ++q) {
        const float* cb   = cbs + (size_t)q * BINS * DIM;
        const float* cbsq = g_cbsq + q * BINS;

        float best[8];
        int   bidx[8];
        #pragma unroll
        for (int im = 0; im < 8; ++im) { best[im] = 3.4e38f; bidx[im] = 0; }

        for (int jc = 0; jc < BINS / NC; ++jc) {  // 8 chunks, ascending j
            const int j0 = jc * NC;
            float acc[8][8];
            #pragma unroll
            for (int im = 0; im < 8; ++im)
                #pragma unroll
                for (int ij = 0; ij < 8; ++ij) acc[im][ij] = 0.f;

            // Preload slice 0 into buffer 0 (transpose to [kk][j])
            {
                const float* src = cb + (size_t)(j0 + lj) * DIM + lg * 4;
                #pragma unroll
                for (int p = 0; p < 4; ++p) {
                    float4 v = *(const float4*)(src + (size_t)(p * 32) * DIM);
                    int row = p * 32 + lj;
                    Csm[(lg * 4 + 0) * NC + row] = v.x;
                    Csm[(lg * 4 + 1) * NC + row] = v.y;
                    Csm[(lg * 4 + 2) * NC + row] = v.z;
                    Csm[(lg * 4 + 3) * NC + row] = v.w;
                }
            }
            __syncthreads();

            for (int s = 0; s < DIM / KSL; ++s) {   // 8 K-slices
                float4 n0, n1, n2, n3;
                if (s < 7) {
                    const float* src = cb + (size_t)(j0 + lj) * DIM + (s + 1) * KSL + lg * 4;
                    n0 = *(const float4*)(src + (size_t)(0 * 32) * DIM);
                    n1 = *(const float4*)(src + (size_t)(1 * 32) * DIM);
                    n2 = *(const float4*)(src + (size_t)(2 * 32) * DIM);
                    n3 = *(const float4*)(src + (size_t)(3 * 32) * DIM);
                }
                const float* Cb = Csm + (s & 1) * (KSL * NC);
                const float* Rb = Rsm + s * KSL * RS;
                #pragma unroll 8
                for (int kk = 0; kk < KSL; ++kk) {
                    float4 a0 = *(const float4*)(Rb + kk * RS + aoff);
                    float4 a1 = *(const float4*)(Rb + kk * RS + aoff + 4);
                    float4 b0 = *(const float4*)(Cb + kk * NC + boff);
                    float4 b1 = *(const float4*)(Cb + kk * NC + boff + 4);
                    float av[8] = {a0.x, a0.y, a0.z, a0.w, a1.x, a1.y, a1.z, a1.w};
                    float bv[8] = {b0.x, b0.y, b0.z, b0.w, b1.x, b1.y, b1.z, b1.w};
                    #pragma unroll
                    for (int im = 0; im < 8; ++im)
                        #pragma unroll
                        for (int ij = 0; ij < 8; ++ij)
                            acc[im][ij] = fmaf(av[im], bv[ij], acc[im][ij]);
                }
                if (s < 7) {
                    float* dst = Csm + ((s + 1) & 1) * (KSL * NC);
                    #pragma unroll
                    for (int p = 0; p < 4; ++p) {
                        int row = p * 32 + lj;
                        float4 v = (p == 0) ? n0 : (p == 1) ? n1 : (p == 2) ? n2 : n3;
                        dst[(lg * 4 + 0) * NC + row] = v.x;
                        dst[(lg * 4 + 1) * NC + row] = v.y;
                        dst[(lg * 4 + 2) * NC + row] = v.z;
                        dst[(lg * 4 + 3) * NC + row] = v.w;
                    }
                }
                __syncthreads();
            }

            // Epilogue: dist = cb_sq[j] - 2*dot ; running argmin (j ascending)
            #pragma unroll
            for (int ij = 0; ij < 8; ++ij) {
                int j = j0 + boff + ij;
                float cq = cbsq[j];
                #pragma unroll
                for (int im = 0; im < 8; ++im) {
                    float dist = cq - 2.0f * acc[im][ij];
                    if (dist < best[im]) { best[im] = dist; bidx[im] = j; }
                }
            }
        }

        // Cross-thread argmin reduction per token (16 tj-partials each)
        #pragma unroll
        for (int im = 0; im < 8; ++im) {
            redv[(aoff + im) * 16 + tj] = best[im];
            redi[(aoff + im) * 16 + tj] = bidx[im];
        }
        __syncthreads();
        if (tid < MT) {
            float bv = redv[tid * 16];
            int   bi = redi[tid * 16];
            #pragma unroll
            for (int r = 1; r < 16; ++r) {
                float v = redv[tid * 16 + r];
                int   ix = redi[tid * 16 + r];
                if (v < bv || (v == bv && ix < bi)) { bv = v; bi = ix; }
            }
            sidx[tid] = bi;
            // codes[q][b][t0+tid] as float
            out[QOFF + ((size_t)(q * BB + b)) * TT + t0 + tid] = (float)bi;
        }
        __syncthreads();

        // Residual update: r[d][m] -= cb[idx[m]][d]; accumulate new ssq.
        // tid == d (0..255); coalesced codeword row gathers.
        float ssql = 0.f;
        #pragma unroll 4
        for (int m = 0; m < MT; ++m) {
            int ix = sidx[m];
            float c = __ldg(cb + (size_t)ix * DIM + tid);
            float r = Rsm[tid * RS + m] - c;
            Rsm[tid * RS + m] = r;
            ssql = fmaf(r, r, ssql);
        }
        ssqs[tid] = ssql;
        __syncthreads();
        if (tid == 0) {
            float s = 0.f;
            for (int i = 0; i < 256; ++i) s += ssqs[i];
            g_ssq[q * NBLK + bid] = s;
        }
        __syncthreads();
    }

    // quantized = x - r_final, written back in [B][D][T] layout (coalesced)
    for (int i = tid; i < DIM * MT; i += 256) {
        int d = i >> 7, m = i & 127;
        out[((size_t)b * DIM + d) * TT + t0 + m] =
            xblk[(size_t)d * TT + m] - Rsm[d * RS + m];
    }
}

// ---------------------------------------------------------------------------
// Kernel 3: finalize scalars (deterministic fixed-order reduction)
// ---------------------------------------------------------------------------
__global__ void rvq_finalize_kernel(const int* __restrict__ sr_raw,
                                    float* __restrict__ out) {
    if (threadIdx.x != 0 || blockIdx.x != 0) return;
    float total = 0.f;
    for (int q = 0; q < NQ; ++q) {
        float s = 0.f;
        for (int i = 0; i < NBLK; ++i) s += g_ssq[q * NBLK + i];
        total += 0.25f * (s / (float)(NTOK * DIM));
    }
    // sample_rate: int32 expected; fall back to float bit-pattern heuristic
    int   iv = sr_raw[0];
    float sr;
    if (iv > 0 && iv < 100000000) sr = (float)iv;
    else                          sr = __int_as_float(iv);
    out[COFF + 0] = (float)NQ * 10.0f * (sr / 1000.0f);  // log2(1024)=10
    out[COFF + 1] = total / (float)NQ;
}

// ---------------------------------------------------------------------------
extern "C" void kernel_launch(void* const* d_in, const int* in_sizes, int n_in,
                              void* d_out, int out_size) {
    const float* x   = (const float*)d_in[0];
    const int*   sr  = (const int*)d_in[1];
    const float* cbs = (const float*)d_in[2];
    float* out = (float*)d_out;

    cudaFuncSetAttribute(rvq_main_kernel,
                         cudaFuncAttributeMaxDynamicSharedMemorySize, SM_BYTES);

    rvq_cbsq_kernel<<<(NQ * BINS + 255) / 256, 256>>>(cbs);
    rvq_main_kernel<<<NBLK, 256, SM_BYTES>>>(x, cbs, out);
    rvq_finalize_kernel<<<1, 32>>>(sr, out);
}